// round 1
// baseline (speedup 1.0000x reference)
#include <cuda_runtime.h>
#include <cuda_bf16.h>

#define NEG_DEFAULT (-10000.0f)

// One row (K=64) handled by 16 lanes, 4 elements each (int4/float4).
// Two rows per warp. cond is uniform within each 16-lane group.
__global__ void __launch_bounds__(256)
dgb_kernel(const float4* __restrict__ dist4,
           const int4*  __restrict__ nidx4,
           const float* __restrict__ score,
           float4* __restrict__ dist_out4,
           float4* __restrict__ nidx_out4,
           int V)
{
    long long gtid = (long long)blockIdx.x * blockDim.x + threadIdx.x;
    long long row  = gtid >> 4;            // 16 lanes per row
    if (row >= V) return;
    int sub  = (int)(gtid & 15);           // lane within row: 0..15

    long long base = row * 16 + sub;       // index into [V,16] of 4-vectors

    int4 ni = nidx4[base];

    // Gather neighbour scores; column 0 (self) excluded from the max.
    float a = (sub == 0)  ? NEG_DEFAULT : ((ni.x < 0) ? NEG_DEFAULT : __ldg(&score[ni.x]));
    float b = (ni.y < 0)  ? NEG_DEFAULT : __ldg(&score[ni.y]);
    float c = (ni.z < 0)  ? NEG_DEFAULT : __ldg(&score[ni.z]);
    float d = (ni.w < 0)  ? NEG_DEFAULT : __ldg(&score[ni.w]);
    float m = fmaxf(fmaxf(a, b), fmaxf(c, d));

    // Reduce max over the 16 lanes of this row. xor offsets 8,4,2,1 stay
    // within each half-warp, so the two rows in a warp reduce independently.
    #pragma unroll
    for (int o = 8; o > 0; o >>= 1)
        m = fmaxf(m, __shfl_xor_sync(0xFFFFFFFFu, m, o));

    float sv = __ldg(&score[row]);
    bool cond = (sv - m) < 0.0f;   // uniform across the 16 lanes

    if (cond) {
        dist_out4[base] = make_float4(0.f, 0.f, 0.f, 0.f);
        if (sub == 0)
            nidx_out4[base] = make_float4((float)row, -1.f, -1.f, -1.f);
        else
            nidx_out4[base] = make_float4(-1.f, -1.f, -1.f, -1.f);
    } else {
        dist_out4[base] = dist4[base];   // dist read only on ~1.6% of rows
        nidx_out4[base] = make_float4((float)ni.x, (float)ni.y,
                                      (float)ni.z, (float)ni.w);
    }
}

extern "C" void kernel_launch(void* const* d_in, const int* in_sizes, int n_in,
                              void* d_out, int out_size)
{
    const float* dist  = (const float*)d_in[0];   // [V, 64] f32
    const int*   nidx  = (const int*)d_in[1];     // [V, 64] i32
    const float* score = (const float*)d_in[2];   // [V, 1]  f32

    int V = in_sizes[2];                          // score element count == V

    float* out      = (float*)d_out;
    float* dist_out = out;                        // first V*64 floats
    float* nidx_out = out + (long long)V * 64;    // second V*64 (ints as f32)

    long long total_threads = (long long)V * 16;  // 16 lanes per row
    int threads = 256;
    long long blocks = (total_threads + threads - 1) / threads;

    dgb_kernel<<<(unsigned int)blocks, threads>>>(
        (const float4*)dist, (const int4*)nidx, score,
        (float4*)dist_out, (float4*)nidx_out, V);
}

// round 2
// speedup vs baseline: 2.5561x; 2.5561x over previous
#include <cuda_runtime.h>
#include <cuda_bf16.h>

#define FULL_MASK 0xFFFFFFFFu

// 4 lanes per row, 8 rows per warp. Early-exit scan over neighbour columns
// in chunks of 4: stop as soon as any neighbour score beats score[row].
// Expected gathers/row ~7.3 instead of 63 (uniform scores), so the L1tex
// gather-wavefront bottleneck from R1 collapses. Rows that early-exit
// (98.4%) never read the rest of their nidx row, nor their dist row.
__global__ void __launch_bounds__(256)
dgb_kernel(const float4* __restrict__ dist4,
           const int*    __restrict__ nidx,
           const float*  __restrict__ score,
           float4* __restrict__ dist_out4,
           float4* __restrict__ nidx_out4,
           long long V)
{
    long long warp_id = ((long long)blockIdx.x * blockDim.x + threadIdx.x) >> 5;
    int lane = threadIdx.x & 31;
    int g = lane >> 2;          // group (row) within warp: 0..7
    int l = lane & 3;           // lane within group: 0..3

    long long row = warp_id * 8 + g;
    bool valid = row < V;

    float sv = valid ? __ldg(score + row) : 0.0f;

    bool undecided = valid;
    bool cond = false;          // true => a neighbour beats sv

    const int* nrow = nidx + row * 64;

    #pragma unroll 1
    for (int j = 0; j < 16; ++j) {
        if (!__ballot_sync(FULL_MASK, undecided)) break;
        bool beat = false;
        if (undecided) {
            int col = (j << 2) + l;
            int ni = __ldg(nrow + col);
            if (col != 0 && ni >= 0) {          // column 0 is self: excluded
                beat = __ldg(score + ni) > sv;  // strict, matches diff < 0
            }
        }
        unsigned b = __ballot_sync(FULL_MASK, beat);
        if (undecided && ((b >> (g << 2)) & 0xFu)) {
            cond = true;
            undecided = false;
        }
    }
    // undecided after full scan => no neighbour beats sv => cond stays false

    if (!valid) return;

    long long base = row * 16;   // row start, in float4 units (K=64 floats)

    if (cond) {
        // dist row -> zeros; nidx row -> [row, -1, -1, ...]
        const float4 z   = make_float4(0.f, 0.f, 0.f, 0.f);
        #pragma unroll
        for (int t = 0; t < 4; ++t)
            dist_out4[base + t * 4 + l] = z;
        #pragma unroll
        for (int t = 0; t < 4; ++t) {
            float4 v = make_float4(-1.f, -1.f, -1.f, -1.f);
            if (t == 0 && l == 0) v.x = (float)row;
            nidx_out4[base + t * 4 + l] = v;
        }
    } else {
        // pass-through: copy dist, convert nidx int -> float
        const int4* nidx4 = (const int4*)nidx;
        #pragma unroll
        for (int t = 0; t < 4; ++t) {
            long long idx = base + t * 4 + l;
            float4 dv = __ldg(dist4 + idx);
            int4   ni = __ldg(nidx4 + idx);
            dist_out4[idx] = dv;
            nidx_out4[idx] = make_float4((float)ni.x, (float)ni.y,
                                         (float)ni.z, (float)ni.w);
        }
    }
}

extern "C" void kernel_launch(void* const* d_in, const int* in_sizes, int n_in,
                              void* d_out, int out_size)
{
    const float* dist  = (const float*)d_in[0];   // [V, 64] f32
    const int*   nidx  = (const int*)d_in[1];     // [V, 64] i32
    const float* score = (const float*)d_in[2];   // [V, 1]  f32

    long long V = in_sizes[2];                    // score element count == V

    float* out      = (float*)d_out;
    float* dist_out = out;                        // first V*64 floats
    float* nidx_out = out + V * 64;               // second V*64 (ints as f32)

    // 4 lanes per row -> V*4 threads
    long long total_threads = V * 4;
    int threads = 256;
    long long blocks = (total_threads + threads - 1) / threads;

    dgb_kernel<<<(unsigned int)blocks, threads>>>(
        (const float4*)dist, nidx, score,
        (float4*)dist_out, (float4*)nidx_out, V);
}

// round 3
// speedup vs baseline: 2.6074x; 1.0200x over previous
#include <cuda_runtime.h>
#include <cuda_bf16.h>

#define FULL_MASK 0xFFFFFFFFu

// Phase 1 (decide): 4 lanes per row, 8 rows per warp, early-exit scan of the
// 64 neighbour columns in chunks of 4; stop as soon as any neighbour score
// beats score[row]. Per-group __any_sync lets each row exit independently.
// Phase 2 (write): warp streams its 8 contiguous rows (8*64 floats = 128
// float4) in 4 perfectly-coalesced 512B store instructions per array,
// selecting per-element values from the 8-bit cond mask.
__global__ void __launch_bounds__(256)
dgb_kernel(const float4* __restrict__ dist4,
           const int*    __restrict__ nidx,
           const float*  __restrict__ score,
           float4* __restrict__ dist_out4,
           float4* __restrict__ nidx_out4,
           long long V)
{
    long long warp_id = ((long long)blockIdx.x * blockDim.x + threadIdx.x) >> 5;
    int lane = threadIdx.x & 31;
    int g = lane >> 2;            // row group within warp: 0..7
    int l = lane & 3;             // lane within group: 0..3
    unsigned grpmask = 0xFu << (g << 2);

    long long row = warp_id * 8 + g;
    bool valid = row < V;

    float sv = valid ? __ldg(score + row) : 3.0f;   // sv>1 => never beaten
    const int* nrow = nidx + row * 64;

    bool cond = false;            // true => some neighbour beats sv
    if (valid) {
        #pragma unroll 1
        for (int j = 0; j < 16; ++j) {
            int col = (j << 2) + l;
            int ni = __ldg(nrow + col);
            bool beat = false;
            if (col != 0 && ni >= 0)
                beat = __ldg(score + ni) > sv;   // strict, matches diff < 0
            if (__any_sync(grpmask, beat)) { cond = true; break; }
        }
    }

    // Publish cond bits for all 8 rows of this warp (bit at lane g*4).
    unsigned bal = __ballot_sync(FULL_MASK, cond);

    // ---- write phase: contiguous streaming over the warp's 8 rows ----
    long long warp_row0 = warp_id * 8;
    long long gbase = warp_row0 * 16;            // float4 index of region start
    const int4* nidx4 = (const int4*)nidx;

    #pragma unroll
    for (int t = 0; t < 4; ++t) {
        int vec = t * 32 + lane;                 // 0..127 within warp region
        int row_local = vec >> 4;                // 0..7
        int within = vec & 15;                   // float4 within row
        long long r = warp_row0 + row_local;
        if (r >= V) break;                        // uniform tail guard per t? not uniform; use continue
        long long idx = gbase + vec;

        bool c = (bal >> (row_local << 2)) & 1u;

        float4 dv, nv;
        if (c) {
            dv = make_float4(0.f, 0.f, 0.f, 0.f);
            nv = make_float4(-1.f, -1.f, -1.f, -1.f);
            if (within == 0) nv.x = (float)r;
        } else {
            dv = __ldg(dist4 + idx);
            int4 ni = __ldg(nidx4 + idx);
            nv = make_float4((float)ni.x, (float)ni.y,
                             (float)ni.z, (float)ni.w);
        }
        dist_out4[idx] = dv;
        nidx_out4[idx] = nv;
    }
}

extern "C" void kernel_launch(void* const* d_in, const int* in_sizes, int n_in,
                              void* d_out, int out_size)
{
    const float* dist  = (const float*)d_in[0];   // [V, 64] f32
    const int*   nidx  = (const int*)d_in[1];     // [V, 64] i32
    const float* score = (const float*)d_in[2];   // [V, 1]  f32

    long long V = in_sizes[2];                    // score element count == V

    float* out      = (float*)d_out;
    float* dist_out = out;                        // first V*64 floats
    float* nidx_out = out + V * 64;               // second V*64 (ints as f32)

    // 4 lanes per row -> V*4 threads
    long long total_threads = V * 4;
    int threads = 256;
    long long blocks = (total_threads + threads - 1) / threads;

    dgb_kernel<<<(unsigned int)blocks, threads>>>(
        (const float4*)dist, nidx, score,
        (float4*)dist_out, (float4*)nidx_out, V);
}